// round 1
// baseline (speedup 1.0000x reference)
#include <cuda_runtime.h>
#include <math.h>

// Problem constants (fixed shapes): B=8, S=4, Nq=1024, PS=16, H=W=256
#define NPATCH 1024
#define NPROB  32          // B*S
#define SDIM   4
#define WIMG   256
#define EPSB   1e-4f
#define MIN_CORR 6

__device__ float  g_wpatch[NPROB * NPATCH];
__device__ double g_per[NPROB];
__device__ int    g_cnt[NPROB];

// ---------------------------------------------------------------------------
// Kernel 1: w_patch[p, n] = mean_{16x16}( weight / (max(b,1e-4) + 1e-4) )
// One warp per patch (256 elements = 2 float4 per lane). HBM-bound: 67 MB.
// ---------------------------------------------------------------------------
__global__ void k_wpatch(const float* __restrict__ db, const float* __restrict__ dw) {
    int gw   = (blockIdx.x * blockDim.x + threadIdx.x) >> 5;  // global warp = patch id
    int lane = threadIdx.x & 31;
    if (gw >= NPROB * NPATCH) return;
    const float4* b4 = (const float4*)(db) + (size_t)gw * 64;
    const float4* w4 = (const float4*)(dw) + (size_t)gw * 64;
    float acc = 0.f;
#pragma unroll
    for (int c = 0; c < 2; c++) {
        float4 bb = b4[c * 32 + lane];
        float4 ww = w4[c * 32 + lane];
        acc += ww.x / (fmaxf(bb.x, EPSB) + EPSB);
        acc += ww.y / (fmaxf(bb.y, EPSB) + EPSB);
        acc += ww.z / (fmaxf(bb.z, EPSB) + EPSB);
        acc += ww.w / (fmaxf(bb.w, EPSB) + EPSB);
    }
#pragma unroll
    for (int o = 16; o; o >>= 1) acc += __shfl_xor_sync(0xffffffffu, acc, o);
    if (lane == 0) g_wpatch[gw] = acc * (1.f / 256.f);
}

// ---------------------------------------------------------------------------
// Kernel 2: per (b,s) problem — accumulate 40 f64 moments over 1024
// correspondences, then thread 0 solves DLT PnP + 3x3 SVD + pose errors.
// Moments: for m in {w, w*u, w*v, w*(u^2+v^2)}:
//   [m, mX, mY, mZ, mXX, mXY, mXZ, mYY, mYZ, mZZ]
// ---------------------------------------------------------------------------
__global__ __launch_bounds__(256, 1) void k_accum(
    const int*   __restrict__ patch_cls,  // (B,S,N)
    const float* __restrict__ Kmat,       // (B,5,3,3)
    const float* __restrict__ poses,      // (B,5,4,4)
    const float* __restrict__ gt_pose,    // (B,S,4,4)
    const float* __restrict__ depth)      // (B,S,256,256)
{
    int prob = blockIdx.x;              // 0..31
    int b = prob / SDIM, s = prob % SDIM;
    int tid = threadIdx.x;

    __shared__ float  sKt[9], sKq[9], sPose[16], sGt[16];
    __shared__ double sRed[8][40];
    __shared__ int    sCntW[8];
    __shared__ double sMo[40];
    __shared__ int    sCount;

    if (tid < 9)        sKt[tid]      = Kmat[((size_t)b * 5 + (s + 1)) * 9 + tid];
    else if (tid < 18)  sKq[tid - 9]  = Kmat[(size_t)b * 5 * 9 + (tid - 9)];
    else if (tid < 34)  sPose[tid-18] = poses[((size_t)b * 5 + (s + 1)) * 16 + (tid - 18)];
    else if (tid < 50)  sGt[tid-34]   = gt_pose[((size_t)b * SDIM + s) * 16 + (tid - 34)];
    __syncthreads();

    float fx = sKt[0], fy = sKt[4], cx = sKt[2], cy = sKt[5];
    float R00=sPose[0],R01=sPose[1],R02=sPose[2], t0p=sPose[3];
    float R10=sPose[4],R11=sPose[5],R12=sPose[6], t1p=sPose[7];
    float R20=sPose[8],R21=sPose[9],R22=sPose[10],t2p=sPose[11];
    // Rt = R^T, tinv = -R^T t  (f32, mimicking reference)
    float ti0 = -(R00*t0p + R10*t1p + R20*t2p);
    float ti1 = -(R01*t0p + R11*t1p + R21*t2p);
    float ti2 = -(R02*t0p + R12*t1p + R22*t2p);

    double A[4][10];
#pragma unroll
    for (int i = 0; i < 4; i++)
#pragma unroll
        for (int j = 0; j < 10; j++) A[i][j] = 0.0;
    int mcount = 0;

    const int*   pc  = patch_cls + (size_t)prob * NPATCH;
    const float* wp  = g_wpatch  + (size_t)prob * NPATCH;
    const float* dep = depth     + (size_t)prob * (WIMG * WIMG);

    for (int n = tid; n < NPATCH; n += 256) {
        int cls = pc[n];
        bool valid = (cls >= 0) && (cls < NPATCH);
        int buddy = min(max(cls, 0), NPATCH - 1);
        float wpatch = wp[n];
        bool msk = valid && (wpatch > 0.f);
        float w = msk ? wpatch : 0.f;
        mcount += msk ? 1 : 0;

        int bx2 = buddy & 31, by2 = buddy >> 5;
        float cxj = (float)(bx2 * 8 + 4);     // (bx+0.5)*8 exactly
        float cyj = (float)(by2 * 8 + 4);
        float d = dep[(by2 * 8 + 4) * WIMG + (bx2 * 8 + 4)];

        float xn = (cxj - cx) / fx;
        float yn = (cyj - cy) / fy;
        float Xc0 = xn * d, Xc1 = yn * d, Xc2 = d;
        float Xf = R00*Xc0 + R10*Xc1 + R20*Xc2 + ti0;
        float Yf = R01*Xc0 + R11*Xc1 + R21*Xc2 + ti1;
        float Zf = R02*Xc0 + R12*Xc1 + R22*Xc2 + ti2;

        double u = (double)((n & 31) * 8 + 4);
        double v = (double)((n >> 5) * 8 + 4);
        double dw = (double)w;
        double X = (double)Xf, Y = (double)Yf, Z = (double)Zf;

        double mm[4];
        mm[0] = dw; mm[1] = dw * u; mm[2] = dw * v; mm[3] = dw * (u*u + v*v);
        double P10[10];
        P10[0] = 1.0; P10[1] = X; P10[2] = Y; P10[3] = Z;
        P10[4] = X*X; P10[5] = X*Y; P10[6] = X*Z;
        P10[7] = Y*Y; P10[8] = Y*Z; P10[9] = Z*Z;
#pragma unroll
        for (int i = 0; i < 4; i++)
#pragma unroll
            for (int j = 0; j < 10; j++) A[i][j] += mm[i] * P10[j];
    }

    // warp reduce 40 doubles + count
#pragma unroll
    for (int i = 0; i < 4; i++)
#pragma unroll
        for (int j = 0; j < 10; j++) {
            double v = A[i][j];
#pragma unroll
            for (int o = 16; o; o >>= 1) v += __shfl_xor_sync(0xffffffffu, v, o);
            A[i][j] = v;
        }
#pragma unroll
    for (int o = 16; o; o >>= 1) mcount += __shfl_xor_sync(0xffffffffu, mcount, o);

    int wid = tid >> 5;
    if ((tid & 31) == 0) {
#pragma unroll
        for (int i = 0; i < 4; i++)
#pragma unroll
            for (int j = 0; j < 10; j++) sRed[wid][i * 10 + j] = A[i][j];
        sCntW[wid] = mcount;
    }
    __syncthreads();
    if (tid < 40) {
        double v = 0.0;
#pragma unroll
        for (int k = 0; k < 8; k++) v += sRed[k][tid];
        sMo[tid] = v;
    }
    if (tid == 40) {
        int c = 0;
#pragma unroll
        for (int k = 0; k < 8; k++) c += sCntW[k];
        sCount = c;
    }
    __syncthreads();

    if (tid != 0) return;

    // -------- serial tail (f64) --------
    const double* mw = sMo;
    const double* mu = sMo + 10;
    const double* mv = sMo + 20;
    const double* mq = sMo + 30;
    const int SYM[3][3] = {{4,5,6},{5,7,8},{6,8,9}};

    double G[11][11], rhs[11];
    for (int i = 0; i < 11; i++) for (int j = 0; j < 11; j++) G[i][j] = 0.0;
    for (int r = 0; r < 4; r++)
        for (int c = 0; c < 4; c++) {
            double vv;
            if (r < 3 && c < 3)       vv = mw[SYM[r][c]];
            else if (r == 3 && c == 3) vv = mw[0];
            else if (r == 3)           vv = mw[1 + c];
            else                       vv = mw[1 + r];
            G[r][c] = vv; G[4 + r][4 + c] = vv;
        }
    for (int r = 0; r < 4; r++)
        for (int c = 0; c < 3; c++) {
            double vu = (r < 3) ? mu[SYM[r][c]] : mu[1 + c];
            double vv = (r < 3) ? mv[SYM[r][c]] : mv[1 + c];
            G[r][8 + c] = -vu;     G[8 + c][r] = -vu;
            G[4 + r][8 + c] = -vv; G[8 + c][4 + r] = -vv;
        }
    for (int r = 0; r < 3; r++)
        for (int c = 0; c < 3; c++) G[8 + r][8 + c] = mq[SYM[r][c]];
    for (int i = 0; i < 11; i++) G[i][i] += 1e-6;
    for (int r = 0; r < 4; r++) {
        rhs[r]     = (r < 3) ? mu[1 + r] : mu[0];
        rhs[4 + r] = (r < 3) ? mv[1 + r] : mv[0];
    }
    for (int c = 0; c < 3; c++) rhs[8 + c] = -mq[1 + c];

    // Cholesky (G is SPD: A^T W A + 1e-6 I)
    for (int k = 0; k < 11; k++) {
        double dg = G[k][k];
        for (int j = 0; j < k; j++) dg -= G[k][j] * G[k][j];
        dg = sqrt(fmax(dg, 1e-300));
        G[k][k] = dg;
        double inv = 1.0 / dg;
        for (int i = k + 1; i < 11; i++) {
            double v = G[i][k];
            for (int j = 0; j < k; j++) v -= G[i][j] * G[k][j];
            G[i][k] = v * inv;
        }
    }
    double y[11], pv[11];
    for (int i = 0; i < 11; i++) {
        double v = rhs[i];
        for (int j = 0; j < i; j++) v -= G[i][j] * y[j];
        y[i] = v / G[i][i];
    }
    for (int i = 10; i >= 0; i--) {
        double v = y[i];
        for (int j = i + 1; j < 11; j++) v -= G[j][i] * pv[j];
        pv[i] = v / G[i][i];
    }

    double P[3][4];
    for (int i = 0; i < 3; i++)
        for (int j = 0; j < 4; j++) {
            int idx = i * 4 + j;
            P[i][j] = (idx < 11) ? pv[idx] : 1.0;
        }

    // inv(Kq), general 3x3
    double k00=sKq[0],k01=sKq[1],k02=sKq[2];
    double k10=sKq[3],k11=sKq[4],k12=sKq[5];
    double k20=sKq[6],k21=sKq[7],k22=sKq[8];
    double detK = k00*(k11*k22-k12*k21) - k01*(k10*k22-k12*k20) + k02*(k10*k21-k11*k20);
    double idk = 1.0 / detK;
    double iK[3][3] = {
        {(k11*k22-k12*k21)*idk, (k02*k21-k01*k22)*idk, (k01*k12-k02*k11)*idk},
        {(k12*k20-k10*k22)*idk, (k00*k22-k02*k20)*idk, (k02*k10-k00*k12)*idk},
        {(k10*k21-k11*k20)*idk, (k01*k20-k00*k21)*idk, (k00*k11-k01*k10)*idk}};

    double M[3][4];
    for (int i = 0; i < 3; i++)
        for (int j = 0; j < 4; j++)
            M[i][j] = iK[i][0]*P[0][j] + iK[i][1]*P[1][j] + iK[i][2]*P[2][j];

    double dM = M[0][0]*(M[1][1]*M[2][2]-M[1][2]*M[2][1])
              - M[0][1]*(M[1][0]*M[2][2]-M[1][2]*M[2][0])
              + M[0][2]*(M[1][0]*M[2][1]-M[1][1]*M[2][0]);
    double sgn = (dM > 0.0) ? 1.0 : ((dM < 0.0) ? -1.0 : 0.0);
    for (int i = 0; i < 3; i++) for (int j = 0; j < 4; j++) M[i][j] *= sgn;

    // Jacobi eigen of B = M3^T M3
    double Bm[3][3];
    for (int i = 0; i < 3; i++)
        for (int j = 0; j < 3; j++)
            Bm[i][j] = M[0][i]*M[0][j] + M[1][i]*M[1][j] + M[2][i]*M[2][j];
    double V[3][3] = {{1,0,0},{0,1,0},{0,0,1}};
    for (int it = 0; it < 24; it++) {
        double off = Bm[0][1]*Bm[0][1] + Bm[0][2]*Bm[0][2] + Bm[1][2]*Bm[1][2];
        double dia = Bm[0][0]*Bm[0][0] + Bm[1][1]*Bm[1][1] + Bm[2][2]*Bm[2][2];
        if (off <= 1e-28 * (dia + 1e-300)) break;
        int p = (it % 3 == 2) ? 1 : 0;
        int q = (it % 3 == 0) ? 1 : 2;
        double apq = Bm[p][q];
        if (apq == 0.0) continue;
        double theta = (Bm[q][q] - Bm[p][p]) / (2.0 * apq);
        double tJ = ((theta >= 0.0) ? 1.0 : -1.0) / (fabs(theta) + sqrt(theta*theta + 1.0));
        double cJ = 1.0 / sqrt(tJ*tJ + 1.0), sJ = tJ * cJ;
        for (int k = 0; k < 3; k++) {
            double akp = Bm[k][p], akq = Bm[k][q];
            Bm[k][p] = cJ*akp - sJ*akq;
            Bm[k][q] = sJ*akp + cJ*akq;
        }
        for (int k = 0; k < 3; k++) {
            double apk = Bm[p][k], aqk = Bm[q][k];
            Bm[p][k] = cJ*apk - sJ*aqk;
            Bm[q][k] = sJ*apk + cJ*aqk;
        }
        for (int k = 0; k < 3; k++) {
            double vkp = V[k][p], vkq = V[k][q];
            V[k][p] = cJ*vkp - sJ*vkq;
            V[k][q] = sJ*vkp + cJ*vkq;
        }
    }
    double lam[3] = {Bm[0][0], Bm[1][1], Bm[2][2]};
    int idx[3] = {0, 1, 2};
    for (int a = 0; a < 2; a++)
        for (int bb2 = a + 1; bb2 < 3; bb2++)
            if (lam[idx[bb2]] > lam[idx[a]]) { int tmp = idx[a]; idx[a] = idx[bb2]; idx[bb2] = tmp; }
    double Vs[3][3], D[3];
    for (int c = 0; c < 3; c++) {
        D[c] = sqrt(fmax(lam[idx[c]], 0.0));
        for (int r = 0; r < 3; r++) Vs[r][c] = V[r][idx[c]];
    }
    double U[3][3];
    for (int c = 0; c < 3; c++) {
        double u0 = M[0][0]*Vs[0][c] + M[0][1]*Vs[1][c] + M[0][2]*Vs[2][c];
        double u1 = M[1][0]*Vs[0][c] + M[1][1]*Vs[1][c] + M[1][2]*Vs[2][c];
        double u2 = M[2][0]*Vs[0][c] + M[2][1]*Vs[1][c] + M[2][2]*Vs[2][c];
        double nr = sqrt(u0*u0 + u1*u1 + u2*u2);
        double inr = 1.0 / fmax(nr, 1e-300);
        U[0][c] = u0 * inr; U[1][c] = u1 * inr; U[2][c] = u2 * inr;
    }
    double detU = U[0][0]*(U[1][1]*U[2][2]-U[1][2]*U[2][1])
                - U[0][1]*(U[1][0]*U[2][2]-U[1][2]*U[2][0])
                + U[0][2]*(U[1][0]*U[2][1]-U[1][1]*U[2][0]);
    double detV = Vs[0][0]*(Vs[1][1]*Vs[2][2]-Vs[1][2]*Vs[2][1])
                - Vs[0][1]*(Vs[1][0]*Vs[2][2]-Vs[1][2]*Vs[2][0])
                + Vs[0][2]*(Vs[1][0]*Vs[2][1]-Vs[1][1]*Vs[2][0]);
    double dd = (detU * detV >= 0.0) ? 1.0 : -1.0;
    U[0][2] *= dd; U[1][2] *= dd; U[2][2] *= dd;

    double R[3][3];
    for (int i = 0; i < 3; i++)
        for (int j = 0; j < 3; j++)
            R[i][j] = U[i][0]*Vs[j][0] + U[i][1]*Vs[j][1] + U[i][2]*Vs[j][2];

    double meanD = (D[0] + D[1] + D[2]) * (1.0 / 3.0);
    double tp0 = M[0][3] / meanD, tp1 = M[1][3] / meanD, tp2 = M[2][3] / meanD;

    double tr = 0.0;
    for (int i = 0; i < 3; i++)
        for (int j = 0; j < 3; j++)
            tr += R[i][j] * (double)sGt[i * 4 + j];
    double cosang = fmin(fmax((tr - 1.0) * 0.5, -1.0 + 1e-7), 1.0 - 1e-7);
    double rot = acos(cosang);
    double dx = tp0 - (double)sGt[3];
    double dy = tp1 - (double)sGt[7];
    double dz = tp2 - (double)sGt[11];
    double terr = sqrt(dx*dx + dy*dy + dz*dz);

    g_per[prob] = rot + terr;
    g_cnt[prob] = sCount;
}

// ---------------------------------------------------------------------------
// Kernel 3: final scalar reduction over the 32 problems.
// ---------------------------------------------------------------------------
__global__ void k_final(float* out) {
    if (threadIdx.x == 0) {
        double tot = 0.0, cnt = 0.0;
        for (int i = 0; i < NPROB; i++) {
            double c = (g_cnt[i] >= MIN_CORR) ? 1.0 : 0.0;
            tot += g_per[i] * c;
            cnt += c;
        }
        out[0] = (float)(tot / fmax(cnt, 1.0));
    }
}

extern "C" void kernel_launch(void* const* d_in, const int* in_sizes, int n_in,
                              void* d_out, int out_size) {
    // metadata order: dense_flow(0, unused), dense_b(1), dense_weight(2),
    // patch_cls(3), K(4), poses(5), gt_pose(6), template_depth(7)
    const float* dense_b  = (const float*)d_in[1];
    const float* dense_w  = (const float*)d_in[2];
    const int*   pcls     = (const int*)  d_in[3];
    const float* Kmat     = (const float*)d_in[4];
    const float* poses    = (const float*)d_in[5];
    const float* gt       = (const float*)d_in[6];
    const float* depth    = (const float*)d_in[7];

    // 32768 patches, one warp each, 8 warps/block
    k_wpatch<<<4096, 256>>>(dense_b, dense_w);
    k_accum<<<NPROB, 256>>>(pcls, Kmat, poses, gt, depth);
    k_final<<<1, 32>>>((float*)d_out);
}

// round 3
// speedup vs baseline: 1.5088x; 1.5088x over previous
#include <cuda_runtime.h>
#include <math.h>

// Problem constants (fixed shapes): B=8, S=4, Nq=1024, PS=16, H=W=256
#define NPATCH 1024
#define NPROB  32          // B*S
#define SDIM   4
#define WIMG   256
#define EPSB   1e-4f
#define MIN_CORR 6

__device__ float  g_wpatch[NPROB * NPATCH];
__device__ double g_per[NPROB];
__device__ int    g_cnt[NPROB];

// ---------------------------------------------------------------------------
// Kernel 1: w_patch[p, n] = mean_{16x16}( weight / (max(b,1e-4) + 1e-4) )
// One warp per patch (256 elements = 2 float4 per lane). HBM-bound: 67 MB.
// ---------------------------------------------------------------------------
__global__ void k_wpatch(const float* __restrict__ db, const float* __restrict__ dw) {
    int gw   = (blockIdx.x * blockDim.x + threadIdx.x) >> 5;  // global warp = patch id
    int lane = threadIdx.x & 31;
    if (gw >= NPROB * NPATCH) return;
    const float4* b4 = (const float4*)(db) + (size_t)gw * 64;
    const float4* w4 = (const float4*)(dw) + (size_t)gw * 64;
    // issue all 4 wide loads up front (MLP=4)
    float4 b0 = __ldcs(&b4[lane]);
    float4 b1 = __ldcs(&b4[32 + lane]);
    float4 w0 = __ldcs(&w4[lane]);
    float4 w1 = __ldcs(&w4[32 + lane]);
    float acc = 0.f;
    acc += w0.x / (fmaxf(b0.x, EPSB) + EPSB);
    acc += w0.y / (fmaxf(b0.y, EPSB) + EPSB);
    acc += w0.z / (fmaxf(b0.z, EPSB) + EPSB);
    acc += w0.w / (fmaxf(b0.w, EPSB) + EPSB);
    acc += w1.x / (fmaxf(b1.x, EPSB) + EPSB);
    acc += w1.y / (fmaxf(b1.y, EPSB) + EPSB);
    acc += w1.z / (fmaxf(b1.z, EPSB) + EPSB);
    acc += w1.w / (fmaxf(b1.w, EPSB) + EPSB);
#pragma unroll
    for (int o = 16; o; o >>= 1) acc += __shfl_xor_sync(0xffffffffu, acc, o);
    if (lane == 0) g_wpatch[gw] = acc * (1.f / 256.f);
}

// ---------------------------------------------------------------------------
// f64 helpers: LDL^T factor/solve for 4x4 and 3x3 symmetric matrices (no sqrt)
// ---------------------------------------------------------------------------
__device__ __forceinline__ void ldl4_factor(const double S[4][4],
                                            double L[4][4], double D[4], double rD[4]) {
#pragma unroll
    for (int j = 0; j < 4; j++) {
        double d = S[j][j];
#pragma unroll
        for (int k = 0; k < 4; k++) if (k < j) d -= L[j][k] * L[j][k] * D[k];
        D[j] = d; rD[j] = 1.0 / d;
#pragma unroll
        for (int i = 0; i < 4; i++) if (i > j) {
            double v = S[i][j];
#pragma unroll
            for (int k = 0; k < 4; k++) if (k < j) v -= L[i][k] * D[k] * L[j][k];
            L[i][j] = v * rD[j];
        }
    }
}
__device__ __forceinline__ void ldl4_solve(const double L[4][4], const double rD[4],
                                           const double y[4], double x[4]) {
    double z[4];
#pragma unroll
    for (int i = 0; i < 4; i++) {
        double v = y[i];
#pragma unroll
        for (int k = 0; k < 4; k++) if (k < i) v -= L[i][k] * z[k];
        z[i] = v;
    }
#pragma unroll
    for (int i = 0; i < 4; i++) z[i] *= rD[i];
#pragma unroll
    for (int i = 3; i >= 0; i--) {
        double v = z[i];
#pragma unroll
        for (int k = 0; k < 4; k++) if (k > i) v -= L[k][i] * x[k];
        x[i] = v;
    }
}
__device__ __forceinline__ void ldl3_solve(const double S[3][3], const double y[3], double x[3]) {
    double L[3][3], D[3], rD[3];
#pragma unroll
    for (int j = 0; j < 3; j++) {
        double d = S[j][j];
#pragma unroll
        for (int k = 0; k < 3; k++) if (k < j) d -= L[j][k] * L[j][k] * D[k];
        D[j] = d; rD[j] = 1.0 / d;
#pragma unroll
        for (int i = 0; i < 3; i++) if (i > j) {
            double v = S[i][j];
#pragma unroll
            for (int k = 0; k < 3; k++) if (k < j) v -= L[i][k] * D[k] * L[j][k];
            L[i][j] = v * rD[j];
        }
    }
    double z[3];
#pragma unroll
    for (int i = 0; i < 3; i++) {
        double v = y[i];
#pragma unroll
        for (int k = 0; k < 3; k++) if (k < i) v -= L[i][k] * z[k];
        z[i] = v;
    }
#pragma unroll
    for (int i = 0; i < 3; i++) z[i] *= rD[i];
#pragma unroll
    for (int i = 2; i >= 0; i--) {
        double v = z[i];
#pragma unroll
        for (int k = 0; k < 3; k++) if (k > i) v -= L[k][i] * x[k];
        x[i] = v;
    }
}

// eigenvector of symmetric 3x3 B for eigenvalue lam: best-of-3 cross products
__device__ __forceinline__ void eigvec3(const double Bm[3][3], double lam, double v[3]) {
    double r0x = Bm[0][0] - lam, r0y = Bm[0][1],       r0z = Bm[0][2];
    double r1x = Bm[0][1],       r1y = Bm[1][1] - lam, r1z = Bm[1][2];
    double r2x = Bm[0][2],       r2y = Bm[1][2],       r2z = Bm[2][2] - lam;
    double c0x = r0y*r1z - r0z*r1y, c0y = r0z*r1x - r0x*r1z, c0z = r0x*r1y - r0y*r1x;
    double c1x = r0y*r2z - r0z*r2y, c1y = r0z*r2x - r0x*r2z, c1z = r0x*r2y - r0y*r2x;
    double c2x = r1y*r2z - r1z*r2y, c2y = r1z*r2x - r1x*r2z, c2z = r1x*r2y - r1y*r2x;
    double n0 = c0x*c0x + c0y*c0y + c0z*c0z;
    double n1 = c1x*c1x + c1y*c1y + c1z*c1z;
    double n2 = c2x*c2x + c2y*c2y + c2z*c2z;
    double bx = c0x, by = c0y, bz = c0z, bn = n0;
    if (n1 > bn) { bx = c1x; by = c1y; bz = c1z; bn = n1; }
    if (n2 > bn) { bx = c2x; by = c2y; bz = c2z; bn = n2; }
    double inr = 1.0 / sqrt(fmax(bn, 1e-300));
    v[0] = bx * inr; v[1] = by * inr; v[2] = bz * inr;
}

// ---------------------------------------------------------------------------
// Kernel 2: per (b,s) problem — accumulate 40 f64 moments over 1024
// correspondences, then thread 0 runs the (shortened) f64 tail:
// Schur-complement block solve + closed-form 3x3 eigendecomposition.
// ---------------------------------------------------------------------------
__global__ __launch_bounds__(256, 1) void k_accum(
    const int*   __restrict__ patch_cls,  // (B,S,N)
    const float* __restrict__ Kmat,       // (B,5,3,3)
    const float* __restrict__ poses,      // (B,5,4,4)
    const float* __restrict__ gt_pose,    // (B,S,4,4)
    const float* __restrict__ depth)      // (B,S,256,256)
{
    int prob = blockIdx.x;              // 0..31
    int b = prob / SDIM, s = prob % SDIM;
    int tid = threadIdx.x;

    __shared__ float  sKt[9], sKq[9], sPose[16], sGt[16];
    __shared__ double sRed[8][40];
    __shared__ int    sCntW[8];
    __shared__ double sMo[40];
    __shared__ int    sCount;

    if (tid < 9)        sKt[tid]      = Kmat[((size_t)b * 5 + (s + 1)) * 9 + tid];
    else if (tid < 18)  sKq[tid - 9]  = Kmat[(size_t)b * 5 * 9 + (tid - 9)];
    else if (tid < 34)  sPose[tid-18] = poses[((size_t)b * 5 + (s + 1)) * 16 + (tid - 18)];
    else if (tid < 50)  sGt[tid-34]   = gt_pose[((size_t)b * SDIM + s) * 16 + (tid - 34)];
    __syncthreads();

    float fx = sKt[0], fy = sKt[4], cx = sKt[2], cy = sKt[5];
    float R00=sPose[0],R01=sPose[1],R02=sPose[2], t0p=sPose[3];
    float R10=sPose[4],R11=sPose[5],R12=sPose[6], t1p=sPose[7];
    float R20=sPose[8],R21=sPose[9],R22=sPose[10],t2p=sPose[11];
    float ti0 = -(R00*t0p + R10*t1p + R20*t2p);
    float ti1 = -(R01*t0p + R11*t1p + R21*t2p);
    float ti2 = -(R02*t0p + R12*t1p + R22*t2p);

    double A[4][10];
#pragma unroll
    for (int i = 0; i < 4; i++)
#pragma unroll
        for (int j = 0; j < 10; j++) A[i][j] = 0.0;
    int mcount = 0;

    const int*   pc  = patch_cls + (size_t)prob * NPATCH;
    const float* wp  = g_wpatch  + (size_t)prob * NPATCH;
    const float* dep = depth     + (size_t)prob * (WIMG * WIMG);

    for (int n = tid; n < NPATCH; n += 256) {
        int cls = pc[n];
        bool valid = (cls >= 0) && (cls < NPATCH);
        int buddy = min(max(cls, 0), NPATCH - 1);
        float wpatch = wp[n];
        bool msk = valid && (wpatch > 0.f);
        float w = msk ? wpatch : 0.f;
        mcount += msk ? 1 : 0;

        int bx2 = buddy & 31, by2 = buddy >> 5;
        float cxj = (float)(bx2 * 8 + 4);
        float cyj = (float)(by2 * 8 + 4);
        float d = dep[(by2 * 8 + 4) * WIMG + (bx2 * 8 + 4)];

        float xn = (cxj - cx) / fx;
        float yn = (cyj - cy) / fy;
        float Xc0 = xn * d, Xc1 = yn * d, Xc2 = d;
        float Xf = R00*Xc0 + R10*Xc1 + R20*Xc2 + ti0;
        float Yf = R01*Xc0 + R11*Xc1 + R21*Xc2 + ti1;
        float Zf = R02*Xc0 + R12*Xc1 + R22*Xc2 + ti2;

        double u = (double)((n & 31) * 8 + 4);
        double v = (double)((n >> 5) * 8 + 4);
        double dw = (double)w;
        double X = (double)Xf, Y = (double)Yf, Z = (double)Zf;

        double mm[4];
        mm[0] = dw; mm[1] = dw * u; mm[2] = dw * v; mm[3] = dw * (u*u + v*v);
        double P10[10];
        P10[0] = 1.0; P10[1] = X; P10[2] = Y; P10[3] = Z;
        P10[4] = X*X; P10[5] = X*Y; P10[6] = X*Z;
        P10[7] = Y*Y; P10[8] = Y*Z; P10[9] = Z*Z;
#pragma unroll
        for (int i = 0; i < 4; i++)
#pragma unroll
            for (int j = 0; j < 10; j++) A[i][j] += mm[i] * P10[j];
    }

#pragma unroll
    for (int i = 0; i < 4; i++)
#pragma unroll
        for (int j = 0; j < 10; j++) {
            double v = A[i][j];
#pragma unroll
            for (int o = 16; o; o >>= 1) v += __shfl_xor_sync(0xffffffffu, v, o);
            A[i][j] = v;
        }
#pragma unroll
    for (int o = 16; o; o >>= 1) mcount += __shfl_xor_sync(0xffffffffu, mcount, o);

    int wid = tid >> 5;
    if ((tid & 31) == 0) {
#pragma unroll
        for (int i = 0; i < 4; i++)
#pragma unroll
            for (int j = 0; j < 10; j++) sRed[wid][i * 10 + j] = A[i][j];
        sCntW[wid] = mcount;
    }
    __syncthreads();
    if (tid < 40) {
        double v = 0.0;
#pragma unroll
        for (int k = 0; k < 8; k++) v += sRed[k][tid];
        sMo[tid] = v;
    }
    if (tid == 40) {
        int c = 0;
#pragma unroll
        for (int k = 0; k < 8; k++) c += sCntW[k];
        sCount = c;
    }
    __syncthreads();

    if (tid != 0) return;

    // ================= serial tail (f64, shortened critical path) ==========
    const double* mw = sMo;
    const double* mu = sMo + 10;
    const double* mv = sMo + 20;
    const double* mq = sMo + 30;
    const int SYM[3][3] = {{4,5,6},{5,7,8},{6,8,9}};

    // Block structure of G = [[S,0,Ub],[0,S,Vb],[Ub^T,Vb^T,C]] (+1e-6 I)
    double S[4][4], Ub[4][3], Vb[4][3], Cm[3][3], ru[4], rv[4], rc[3];
#pragma unroll
    for (int r = 0; r < 4; r++)
#pragma unroll
        for (int c = 0; c < 4; c++) {
            double vv;
            if (r < 3 && c < 3)        vv = mw[SYM[r][c]];
            else if (r == 3 && c == 3) vv = mw[0];
            else if (r == 3)           vv = mw[1 + c];
            else                       vv = mw[1 + r];
            S[r][c] = vv;
        }
#pragma unroll
    for (int i = 0; i < 4; i++) S[i][i] += 1e-6;
#pragma unroll
    for (int r = 0; r < 4; r++)
#pragma unroll
        for (int c = 0; c < 3; c++) {
            Ub[r][c] = -((r < 3) ? mu[SYM[r][c]] : mu[1 + c]);
            Vb[r][c] = -((r < 3) ? mv[SYM[r][c]] : mv[1 + c]);
        }
#pragma unroll
    for (int r = 0; r < 3; r++)
#pragma unroll
        for (int c = 0; c < 3; c++) Cm[r][c] = mq[SYM[r][c]];
#pragma unroll
    for (int i = 0; i < 3; i++) Cm[i][i] += 1e-6;
#pragma unroll
    for (int r = 0; r < 4; r++) {
        ru[r] = (r < 3) ? mu[1 + r] : mu[0];
        rv[r] = (r < 3) ? mv[1 + r] : mv[0];
    }
#pragma unroll
    for (int c = 0; c < 3; c++) rc[c] = -mq[1 + c];

    // Factor S once, apply to 8 RHS
    double L4[4][4], D4[4], rD4[4];
    ldl4_factor(S, L4, D4, rD4);

    double YU[4][3], YV[4][3], ya[4], yb[4];
#pragma unroll
    for (int c = 0; c < 3; c++) {
        double col[4], sol[4];
#pragma unroll
        for (int r = 0; r < 4; r++) col[r] = Ub[r][c];
        ldl4_solve(L4, rD4, col, sol);
#pragma unroll
        for (int r = 0; r < 4; r++) YU[r][c] = sol[r];
#pragma unroll
        for (int r = 0; r < 4; r++) col[r] = Vb[r][c];
        ldl4_solve(L4, rD4, col, sol);
#pragma unroll
        for (int r = 0; r < 4; r++) YV[r][c] = sol[r];
    }
    ldl4_solve(L4, rD4, ru, ya);
    ldl4_solve(L4, rD4, rv, yb);

    // Schur complement: Sc = C - Ub^T YU - Vb^T YV; rhs_c = rc - Ub^T ya - Vb^T yb
    double Sc[3][3], rcs[3];
#pragma unroll
    for (int i = 0; i < 3; i++) {
#pragma unroll
        for (int j = 0; j < 3; j++) {
            double v = Cm[i][j];
#pragma unroll
            for (int k = 0; k < 4; k++) v -= Ub[k][i] * YU[k][j] + Vb[k][i] * YV[k][j];
            Sc[i][j] = v;
        }
        double v = rc[i];
#pragma unroll
        for (int k = 0; k < 4; k++) v -= Ub[k][i] * ya[k] + Vb[k][i] * yb[k];
        rcs[i] = v;
    }
    double cv[3];
    ldl3_solve(Sc, rcs, cv);

    double av[4], bv[4];
#pragma unroll
    for (int r = 0; r < 4; r++) {
        av[r] = ya[r] - (YU[r][0]*cv[0] + YU[r][1]*cv[1] + YU[r][2]*cv[2]);
        bv[r] = yb[r] - (YV[r][0]*cv[0] + YV[r][1]*cv[1] + YV[r][2]*cv[2]);
    }

    double P[3][4] = {{av[0],av[1],av[2],av[3]},
                      {bv[0],bv[1],bv[2],bv[3]},
                      {cv[0],cv[1],cv[2],1.0}};

    // inv(Kq), general 3x3
    double k00=sKq[0],k01=sKq[1],k02=sKq[2];
    double k10=sKq[3],k11=sKq[4],k12=sKq[5];
    double k20=sKq[6],k21=sKq[7],k22=sKq[8];
    double detK = k00*(k11*k22-k12*k21) - k01*(k10*k22-k12*k20) + k02*(k10*k21-k11*k20);
    double idk = 1.0 / detK;
    double iK[3][3] = {
        {(k11*k22-k12*k21)*idk, (k02*k21-k01*k22)*idk, (k01*k12-k02*k11)*idk},
        {(k12*k20-k10*k22)*idk, (k00*k22-k02*k20)*idk, (k02*k10-k00*k12)*idk},
        {(k10*k21-k11*k20)*idk, (k01*k20-k00*k21)*idk, (k00*k11-k01*k10)*idk}};

    double M[3][4];
#pragma unroll
    for (int i = 0; i < 3; i++)
#pragma unroll
        for (int j = 0; j < 4; j++)
            M[i][j] = iK[i][0]*P[0][j] + iK[i][1]*P[1][j] + iK[i][2]*P[2][j];

    double dM = M[0][0]*(M[1][1]*M[2][2]-M[1][2]*M[2][1])
              - M[0][1]*(M[1][0]*M[2][2]-M[1][2]*M[2][0])
              + M[0][2]*(M[1][0]*M[2][1]-M[1][1]*M[2][0]);
    double sgn = (dM > 0.0) ? 1.0 : ((dM < 0.0) ? -1.0 : 0.0);
#pragma unroll
    for (int i = 0; i < 3; i++)
#pragma unroll
        for (int j = 0; j < 4; j++) M[i][j] *= sgn;

    // B = M3^T M3, closed-form symmetric eigendecomposition (Cardano)
    double Bm[3][3];
#pragma unroll
    for (int i = 0; i < 3; i++)
#pragma unroll
        for (int j = 0; j < 3; j++)
            Bm[i][j] = M[0][i]*M[0][j] + M[1][i]*M[1][j] + M[2][i]*M[2][j];

    double q3 = (Bm[0][0] + Bm[1][1] + Bm[2][2]) * (1.0/3.0);
    double p1 = Bm[0][1]*Bm[0][1] + Bm[0][2]*Bm[0][2] + Bm[1][2]*Bm[1][2];
    double a0 = Bm[0][0]-q3, a1 = Bm[1][1]-q3, a2 = Bm[2][2]-q3;
    double p2 = a0*a0 + a1*a1 + a2*a2 + 2.0*p1;
    double pJ = sqrt(p2 * (1.0/6.0));
    double pinv = 1.0 / fmax(pJ, 1e-150);
    double c00=a0*pinv, c11=a1*pinv, c22=a2*pinv;
    double c01=Bm[0][1]*pinv, c02=Bm[0][2]*pinv, c12=Bm[1][2]*pinv;
    double detc = c00*(c11*c22-c12*c12) - c01*(c01*c22-c12*c02) + c02*(c01*c12-c11*c02);
    double rr = fmin(fmax(detc * 0.5, -1.0), 1.0);
    double phi = acos(rr) * (1.0/3.0);
    double e1 = q3 + 2.0*pJ*cos(phi);
    double e3 = q3 + 2.0*pJ*cos(phi + 2.0943951023931953);  // +2pi/3
    double e2 = 3.0*q3 - e1 - e3;

    double v1[3], v3[3], v2[3];
    eigvec3(Bm, e1, v1);
    eigvec3(Bm, e3, v3);
    // middle eigenvector: v3 x v1 (orthonormal frame)
    v2[0] = v3[1]*v1[2] - v3[2]*v1[1];
    v2[1] = v3[2]*v1[0] - v3[0]*v1[2];
    v2[2] = v3[0]*v1[1] - v3[1]*v1[0];
    {
        double n2 = v2[0]*v2[0] + v2[1]*v2[1] + v2[2]*v2[2];
        double inr = 1.0 / sqrt(fmax(n2, 1e-300));
        v2[0]*=inr; v2[1]*=inr; v2[2]*=inr;
    }
    double Vs[3][3] = {{v1[0],v2[0],v3[0]},{v1[1],v2[1],v3[1]},{v1[2],v2[2],v3[2]}};
    double D[3] = { sqrt(fmax(e1,0.0)), sqrt(fmax(e2,0.0)), sqrt(fmax(e3,0.0)) };

    double U[3][3];
#pragma unroll
    for (int c = 0; c < 3; c++) {
        double u0 = M[0][0]*Vs[0][c] + M[0][1]*Vs[1][c] + M[0][2]*Vs[2][c];
        double u1 = M[1][0]*Vs[0][c] + M[1][1]*Vs[1][c] + M[1][2]*Vs[2][c];
        double u2 = M[2][0]*Vs[0][c] + M[2][1]*Vs[1][c] + M[2][2]*Vs[2][c];
        double nr = u0*u0 + u1*u1 + u2*u2;
        double inr = 1.0 / sqrt(fmax(nr, 1e-300));
        U[0][c] = u0*inr; U[1][c] = u1*inr; U[2][c] = u2*inr;
    }
    double detU = U[0][0]*(U[1][1]*U[2][2]-U[1][2]*U[2][1])
                - U[0][1]*(U[1][0]*U[2][2]-U[1][2]*U[2][0])
                + U[0][2]*(U[1][0]*U[2][1]-U[1][1]*U[2][0]);
    double detV = Vs[0][0]*(Vs[1][1]*Vs[2][2]-Vs[1][2]*Vs[2][1])
                - Vs[0][1]*(Vs[1][0]*Vs[2][2]-Vs[1][2]*Vs[2][0])
                + Vs[0][2]*(Vs[1][0]*Vs[2][1]-Vs[1][1]*Vs[2][0]);
    double dd = (detU * detV >= 0.0) ? 1.0 : -1.0;
    U[0][2] *= dd; U[1][2] *= dd; U[2][2] *= dd;

    double R[3][3];
#pragma unroll
    for (int i = 0; i < 3; i++)
#pragma unroll
        for (int j = 0; j < 3; j++)
            R[i][j] = U[i][0]*Vs[j][0] + U[i][1]*Vs[j][1] + U[i][2]*Vs[j][2];

    double meanD = (D[0] + D[1] + D[2]) * (1.0/3.0);
    double rmd = 1.0 / meanD;
    double tp0 = M[0][3]*rmd, tp1 = M[1][3]*rmd, tp2 = M[2][3]*rmd;

    double tr = 0.0;
#pragma unroll
    for (int i = 0; i < 3; i++)
#pragma unroll
        for (int j = 0; j < 3; j++)
            tr += R[i][j] * (double)sGt[i * 4 + j];
    double cosang = fmin(fmax((tr - 1.0) * 0.5, -1.0 + 1e-7), 1.0 - 1e-7);
    double rot = acos(cosang);
    double dx = tp0 - (double)sGt[3];
    double dy = tp1 - (double)sGt[7];
    double dz = tp2 - (double)sGt[11];
    double terr = sqrt(dx*dx + dy*dy + dz*dz);

    g_per[prob] = rot + terr;
    g_cnt[prob] = sCount;
}

// ---------------------------------------------------------------------------
// Kernel 3: final scalar reduction over the 32 problems.
// ---------------------------------------------------------------------------
__global__ void k_final(float* out) {
    if (threadIdx.x == 0) {
        double tot = 0.0, cnt = 0.0;
        for (int i = 0; i < NPROB; i++) {
            double c = (g_cnt[i] >= MIN_CORR) ? 1.0 : 0.0;
            tot += g_per[i] * c;
            cnt += c;
        }
        out[0] = (float)(tot / fmax(cnt, 1.0));
    }
}

extern "C" void kernel_launch(void* const* d_in, const int* in_sizes, int n_in,
                              void* d_out, int out_size) {
    const float* dense_b  = (const float*)d_in[1];
    const float* dense_w  = (const float*)d_in[2];
    const int*   pcls     = (const int*)  d_in[3];
    const float* Kmat     = (const float*)d_in[4];
    const float* poses    = (const float*)d_in[5];
    const float* gt       = (const float*)d_in[6];
    const float* depth    = (const float*)d_in[7];

    k_wpatch<<<4096, 256>>>(dense_b, dense_w);
    k_accum<<<NPROB, 256>>>(pcls, Kmat, poses, gt, depth);
    k_final<<<1, 32>>>((float*)d_out);
}

// round 6
// speedup vs baseline: 6.3272x; 4.1937x over previous
#include <cuda_runtime.h>
#include <math.h>

// Problem constants (fixed shapes): B=8, S=4, Nq=1024, PS=16, H=W=256
#define NPATCH 1024
#define NPROB  32          // B*S
#define SDIM   4
#define WIMG   256
#define EPSB   1e-4f
#define MIN_CORR 6
#define USCALE  (1.0f/256.0f)   // pixel-coordinate scaling for conditioning

__device__ float g_wpatch[NPROB * NPATCH];
__device__ float g_per[NPROB];
__device__ int   g_cnt[NPROB];

// ---------------------------------------------------------------------------
// Kernel 1: w_patch = mean_{16x16}( weight / (max(b,1e-4)+1e-4) )
// Two patches per warp -> 8 independent float4 loads in flight per thread.
// ---------------------------------------------------------------------------
__global__ void k_wpatch(const float* __restrict__ db, const float* __restrict__ dw) {
    int gw   = (blockIdx.x * blockDim.x + threadIdx.x) >> 5;  // warp id: patches 2gw, 2gw+1
    int lane = threadIdx.x & 31;
    const float4* b4 = (const float4*)(db) + (size_t)gw * 128;
    const float4* w4 = (const float4*)(dw) + (size_t)gw * 128;
    float4 b0 = __ldcs(b4 + lane);
    float4 b1 = __ldcs(b4 + 32 + lane);
    float4 b2 = __ldcs(b4 + 64 + lane);
    float4 b3 = __ldcs(b4 + 96 + lane);
    float4 w0 = __ldcs(w4 + lane);
    float4 w1 = __ldcs(w4 + 32 + lane);
    float4 w2 = __ldcs(w4 + 64 + lane);
    float4 w3 = __ldcs(w4 + 96 + lane);

    float a0 = 0.f, a1 = 0.f;
    a0 += w0.x / (fmaxf(b0.x, EPSB) + EPSB);
    a0 += w0.y / (fmaxf(b0.y, EPSB) + EPSB);
    a0 += w0.z / (fmaxf(b0.z, EPSB) + EPSB);
    a0 += w0.w / (fmaxf(b0.w, EPSB) + EPSB);
    a0 += w1.x / (fmaxf(b1.x, EPSB) + EPSB);
    a0 += w1.y / (fmaxf(b1.y, EPSB) + EPSB);
    a0 += w1.z / (fmaxf(b1.z, EPSB) + EPSB);
    a0 += w1.w / (fmaxf(b1.w, EPSB) + EPSB);
    a1 += w2.x / (fmaxf(b2.x, EPSB) + EPSB);
    a1 += w2.y / (fmaxf(b2.y, EPSB) + EPSB);
    a1 += w2.z / (fmaxf(b2.z, EPSB) + EPSB);
    a1 += w2.w / (fmaxf(b2.w, EPSB) + EPSB);
    a1 += w3.x / (fmaxf(b3.x, EPSB) + EPSB);
    a1 += w3.y / (fmaxf(b3.y, EPSB) + EPSB);
    a1 += w3.z / (fmaxf(b3.z, EPSB) + EPSB);
    a1 += w3.w / (fmaxf(b3.w, EPSB) + EPSB);
#pragma unroll
    for (int o = 16; o; o >>= 1) {
        a0 += __shfl_xor_sync(0xffffffffu, a0, o);
        a1 += __shfl_xor_sync(0xffffffffu, a1, o);
    }
    if (lane == 0) {
        g_wpatch[2 * gw]     = a0 * (1.f / 256.f);
        g_wpatch[2 * gw + 1] = a1 * (1.f / 256.f);
    }
}

// ---------------------------------------------------------------------------
// f32 LDL^T helpers (no sqrt, fast division)
// ---------------------------------------------------------------------------
__device__ __forceinline__ void ldl4_factor(const float S[4][4],
                                            float L[4][4], float rD[4]) {
    float D[4];
#pragma unroll
    for (int j = 0; j < 4; j++) {
        float d = S[j][j];
#pragma unroll
        for (int k = 0; k < 4; k++) if (k < j) d -= L[j][k] * L[j][k] * D[k];
        D[j] = d; rD[j] = __fdividef(1.0f, d);
#pragma unroll
        for (int i = 0; i < 4; i++) if (i > j) {
            float v = S[i][j];
#pragma unroll
            for (int k = 0; k < 4; k++) if (k < j) v -= L[i][k] * D[k] * L[j][k];
            L[i][j] = v * rD[j];
        }
    }
}
__device__ __forceinline__ void ldl4_solve(const float L[4][4], const float rD[4],
                                           const float y[4], float x[4]) {
    float z[4];
#pragma unroll
    for (int i = 0; i < 4; i++) {
        float v = y[i];
#pragma unroll
        for (int k = 0; k < 4; k++) if (k < i) v -= L[i][k] * z[k];
        z[i] = v;
    }
#pragma unroll
    for (int i = 0; i < 4; i++) z[i] *= rD[i];
#pragma unroll
    for (int i = 3; i >= 0; i--) {
        float v = z[i];
#pragma unroll
        for (int k = 0; k < 4; k++) if (k > i) v -= L[k][i] * x[k];
        x[i] = v;
    }
}
__device__ __forceinline__ void ldl3_solve(const float S[3][3], const float y[3], float x[3]) {
    float L[3][3], D[3], rD[3];
#pragma unroll
    for (int j = 0; j < 3; j++) {
        float d = S[j][j];
#pragma unroll
        for (int k = 0; k < 3; k++) if (k < j) d -= L[j][k] * L[j][k] * D[k];
        D[j] = d; rD[j] = __fdividef(1.0f, d);
#pragma unroll
        for (int i = 0; i < 3; i++) if (i > j) {
            float v = S[i][j];
#pragma unroll
            for (int k = 0; k < 3; k++) if (k < j) v -= L[i][k] * D[k] * L[j][k];
            L[i][j] = v * rD[j];
        }
    }
    float z[3];
#pragma unroll
    for (int i = 0; i < 3; i++) {
        float v = y[i];
#pragma unroll
        for (int k = 0; k < 3; k++) if (k < i) v -= L[i][k] * z[k];
        z[i] = v;
    }
#pragma unroll
    for (int i = 0; i < 3; i++) z[i] *= rD[i];
#pragma unroll
    for (int i = 2; i >= 0; i--) {
        float v = z[i];
#pragma unroll
        for (int k = 0; k < 3; k++) if (k > i) v -= L[k][i] * x[k];
        x[i] = v;
    }
}

// ---------------------------------------------------------------------------
// Kernel 2: per (b,s) problem — 40 f32 scaled moments, then a short f32 tail:
// Schur block solve + determinant-scaled polar Newton for R.
// ---------------------------------------------------------------------------
__global__ __launch_bounds__(256, 1) void k_accum(
    const int*   __restrict__ patch_cls,
    const float* __restrict__ Kmat,       // (B,5,3,3)
    const float* __restrict__ poses,      // (B,5,4,4)
    const float* __restrict__ gt_pose,    // (B,S,4,4)
    const float* __restrict__ depth)      // (B,S,256,256)
{
    int prob = blockIdx.x;
    int b = prob / SDIM, s = prob % SDIM;
    int tid = threadIdx.x;

    __shared__ float sKt[9], sKq[9], sPose[16], sGt[16];
    __shared__ float sRed[8][40];
    __shared__ int   sCntW[8];
    __shared__ float sMo[40];
    __shared__ int   sCount;

    if (tid < 9)        sKt[tid]      = Kmat[((size_t)b * 5 + (s + 1)) * 9 + tid];
    else if (tid < 18)  sKq[tid - 9]  = Kmat[(size_t)b * 5 * 9 + (tid - 9)];
    else if (tid < 34)  sPose[tid-18] = poses[((size_t)b * 5 + (s + 1)) * 16 + (tid - 18)];
    else if (tid < 50)  sGt[tid-34]   = gt_pose[((size_t)b * SDIM + s) * 16 + (tid - 34)];
    __syncthreads();

    float fx = sKt[0], fy = sKt[4], cx = sKt[2], cy = sKt[5];
    float R00=sPose[0],R01=sPose[1],R02=sPose[2], t0p=sPose[3];
    float R10=sPose[4],R11=sPose[5],R12=sPose[6], t1p=sPose[7];
    float R20=sPose[8],R21=sPose[9],R22=sPose[10],t2p=sPose[11];
    float ti0 = -(R00*t0p + R10*t1p + R20*t2p);
    float ti1 = -(R01*t0p + R11*t1p + R21*t2p);
    float ti2 = -(R02*t0p + R12*t1p + R22*t2p);

    float A[4][10];
#pragma unroll
    for (int i = 0; i < 4; i++)
#pragma unroll
        for (int j = 0; j < 10; j++) A[i][j] = 0.f;
    int mcount = 0;

    const int*   pc  = patch_cls + (size_t)prob * NPATCH;
    const float* wp  = g_wpatch  + (size_t)prob * NPATCH;
    const float* dep = depth     + (size_t)prob * (WIMG * WIMG);

    for (int n = tid; n < NPATCH; n += 256) {
        int cls = pc[n];
        bool valid = (cls >= 0) && (cls < NPATCH);
        int buddy = min(max(cls, 0), NPATCH - 1);
        float wpatch = wp[n];
        bool msk = valid && (wpatch > 0.f);
        float w = msk ? wpatch : 0.f;
        mcount += msk ? 1 : 0;

        int bx2 = buddy & 31, by2 = buddy >> 5;
        float cxj = (float)(bx2 * 8 + 4);
        float cyj = (float)(by2 * 8 + 4);
        float d = dep[(by2 * 8 + 4) * WIMG + (bx2 * 8 + 4)];

        float xn = (cxj - cx) / fx;
        float yn = (cyj - cy) / fy;
        float Xc0 = xn * d, Xc1 = yn * d, Xc2 = d;
        float X = R00*Xc0 + R10*Xc1 + R20*Xc2 + ti0;
        float Y = R01*Xc0 + R11*Xc1 + R21*Xc2 + ti1;
        float Z = R02*Xc0 + R12*Xc1 + R22*Xc2 + ti2;

        float u = (float)((n & 31) * 8 + 4) * USCALE;   // scaled pixel coords
        float v = (float)((n >> 5) * 8 + 4) * USCALE;

        float mm[4];
        mm[0] = w; mm[1] = w * u; mm[2] = w * v; mm[3] = w * (u*u + v*v);
        float P10[10];
        P10[0] = 1.f; P10[1] = X; P10[2] = Y; P10[3] = Z;
        P10[4] = X*X; P10[5] = X*Y; P10[6] = X*Z;
        P10[7] = Y*Y; P10[8] = Y*Z; P10[9] = Z*Z;
#pragma unroll
        for (int i = 0; i < 4; i++)
#pragma unroll
            for (int j = 0; j < 10; j++) A[i][j] += mm[i] * P10[j];
    }

#pragma unroll
    for (int i = 0; i < 4; i++)
#pragma unroll
        for (int j = 0; j < 10; j++) {
            float v = A[i][j];
#pragma unroll
            for (int o = 16; o; o >>= 1) v += __shfl_xor_sync(0xffffffffu, v, o);
            A[i][j] = v;
        }
#pragma unroll
    for (int o = 16; o; o >>= 1) mcount += __shfl_xor_sync(0xffffffffu, mcount, o);

    int wid = tid >> 5;
    if ((tid & 31) == 0) {
#pragma unroll
        for (int i = 0; i < 4; i++)
#pragma unroll
            for (int j = 0; j < 10; j++) sRed[wid][i * 10 + j] = A[i][j];
        sCntW[wid] = mcount;
    }
    __syncthreads();
    if (tid < 40) {
        float v = 0.f;
#pragma unroll
        for (int k = 0; k < 8; k++) v += sRed[k][tid];
        sMo[tid] = v;
    }
    if (tid == 40) {
        int c = 0;
#pragma unroll
        for (int k = 0; k < 8; k++) c += sCntW[k];
        sCount = c;
    }
    __syncthreads();

    if (tid != 0) return;

    // ================= f32 tail ==========
    const float* mw = sMo;
    const float* mu = sMo + 10;
    const float* mv = sMo + 20;
    const float* mq = sMo + 30;
    const int SYM[3][3] = {{4,5,6},{5,7,8},{6,8,9}};

    float S[4][4], Ub[4][3], Vb[4][3], Cm[3][3], ru[4], rv[4], rc[3];
#pragma unroll
    for (int r = 0; r < 4; r++)
#pragma unroll
        for (int c = 0; c < 4; c++) {
            float vv;
            if (r < 3 && c < 3)        vv = mw[SYM[r][c]];
            else if (r == 3 && c == 3) vv = mw[0];
            else if (r == 3)           vv = mw[1 + c];
            else                       vv = mw[1 + r];
            S[r][c] = vv;
        }
#pragma unroll
    for (int i = 0; i < 4; i++) S[i][i] += 1e-6f;
#pragma unroll
    for (int r = 0; r < 4; r++)
#pragma unroll
        for (int c = 0; c < 3; c++) {
            Ub[r][c] = -((r < 3) ? mu[SYM[r][c]] : mu[1 + c]);
            Vb[r][c] = -((r < 3) ? mv[SYM[r][c]] : mv[1 + c]);
        }
#pragma unroll
    for (int r = 0; r < 3; r++)
#pragma unroll
        for (int c = 0; c < 3; c++) Cm[r][c] = mq[SYM[r][c]];
#pragma unroll
    for (int i = 0; i < 3; i++) Cm[i][i] += 1e-6f;
#pragma unroll
    for (int r = 0; r < 4; r++) {
        ru[r] = (r < 3) ? mu[1 + r] : mu[0];
        rv[r] = (r < 3) ? mv[1 + r] : mv[0];
    }
#pragma unroll
    for (int c = 0; c < 3; c++) rc[c] = -mq[1 + c];

    float L4[4][4], rD4[4];
    ldl4_factor(S, L4, rD4);

    float YU[4][3], YV[4][3], ya[4], yb[4];
#pragma unroll
    for (int c = 0; c < 3; c++) {
        float col[4], sol[4];
#pragma unroll
        for (int r = 0; r < 4; r++) col[r] = Ub[r][c];
        ldl4_solve(L4, rD4, col, sol);
#pragma unroll
        for (int r = 0; r < 4; r++) YU[r][c] = sol[r];
#pragma unroll
        for (int r = 0; r < 4; r++) col[r] = Vb[r][c];
        ldl4_solve(L4, rD4, col, sol);
#pragma unroll
        for (int r = 0; r < 4; r++) YV[r][c] = sol[r];
    }
    ldl4_solve(L4, rD4, ru, ya);
    ldl4_solve(L4, rD4, rv, yb);

    float Sc[3][3], rcs[3];
#pragma unroll
    for (int i = 0; i < 3; i++) {
#pragma unroll
        for (int j = 0; j < 3; j++) {
            float v = Cm[i][j];
#pragma unroll
            for (int k = 0; k < 4; k++) v -= Ub[k][i] * YU[k][j] + Vb[k][i] * YV[k][j];
            Sc[i][j] = v;
        }
        float v = rc[i];
#pragma unroll
        for (int k = 0; k < 4; k++) v -= Ub[k][i] * ya[k] + Vb[k][i] * yb[k];
        rcs[i] = v;
    }
    float cv[3];
    ldl3_solve(Sc, rcs, cv);

    float av[4], bv[4];
#pragma unroll
    for (int r = 0; r < 4; r++) {
        av[r] = ya[r] - (YU[r][0]*cv[0] + YU[r][1]*cv[1] + YU[r][2]*cv[2]);
        bv[r] = yb[r] - (YV[r][0]*cv[0] + YV[r][1]*cv[1] + YV[r][2]*cv[2]);
    }
    // unscale: first 8 solution components multiply by 1/USCALE = 256
#pragma unroll
    for (int r = 0; r < 4; r++) { av[r] *= 256.f; bv[r] *= 256.f; }

    float P[3][4] = {{av[0],av[1],av[2],av[3]},
                     {bv[0],bv[1],bv[2],bv[3]},
                     {cv[0],cv[1],cv[2],1.f}};

    // inv(Kq)
    float k00=sKq[0],k01=sKq[1],k02=sKq[2];
    float k10=sKq[3],k11=sKq[4],k12=sKq[5];
    float k20=sKq[6],k21=sKq[7],k22=sKq[8];
    float detK = k00*(k11*k22-k12*k21) - k01*(k10*k22-k12*k20) + k02*(k10*k21-k11*k20);
    float idk = __fdividef(1.f, detK);
    float iK[3][3] = {
        {(k11*k22-k12*k21)*idk, (k02*k21-k01*k22)*idk, (k01*k12-k02*k11)*idk},
        {(k12*k20-k10*k22)*idk, (k00*k22-k02*k20)*idk, (k02*k10-k00*k12)*idk},
        {(k10*k21-k11*k20)*idk, (k01*k20-k00*k21)*idk, (k00*k11-k01*k10)*idk}};

    float M[3][4];
#pragma unroll
    for (int i = 0; i < 3; i++)
#pragma unroll
        for (int j = 0; j < 4; j++)
            M[i][j] = iK[i][0]*P[0][j] + iK[i][1]*P[1][j] + iK[i][2]*P[2][j];

    float dM = M[0][0]*(M[1][1]*M[2][2]-M[1][2]*M[2][1])
             - M[0][1]*(M[1][0]*M[2][2]-M[1][2]*M[2][0])
             + M[0][2]*(M[1][0]*M[2][1]-M[1][1]*M[2][0]);
    float sg = (dM > 0.f) ? 1.f : ((dM < 0.f) ? -1.f : 0.f);
#pragma unroll
    for (int i = 0; i < 3; i++)
#pragma unroll
        for (int j = 0; j < 4; j++) M[i][j] *= sg;

    // Polar decomposition of M3 via DETERMINANT-SCALED Newton (Higham):
    //   X <- 0.5( g*X + (1/g) * X^{-T} ),  g = |det X|^{-1/3}
    // U,V of the SVD are invariant under the iteration; singular values -> 1,
    // so X -> U V^T = R (det>0 after the sign flip above).
    // mean(D) = trace(R^T M3)/3.
    float fro = 0.f;
#pragma unroll
    for (int i = 0; i < 3; i++)
#pragma unroll
        for (int j = 0; j < 3; j++) fro += M[i][j] * M[i][j];
    float s0i = rsqrtf(fmaxf(fro * (1.f/3.f), 1e-30f));
    float X00=M[0][0]*s0i, X01=M[0][1]*s0i, X02=M[0][2]*s0i;
    float X10=M[1][0]*s0i, X11=M[1][1]*s0i, X12=M[1][2]*s0i;
    float X20=M[2][0]*s0i, X21=M[2][1]*s0i, X22=M[2][2]*s0i;
#pragma unroll
    for (int it = 0; it < 6; it++) {
        float c00 = X11*X22 - X12*X21;
        float c01 = X12*X20 - X10*X22;
        float c02 = X10*X21 - X11*X20;
        float c10 = X02*X21 - X01*X22;
        float c11 = X00*X22 - X02*X20;
        float c12 = X01*X20 - X00*X21;
        float c20 = X01*X12 - X02*X11;
        float c21 = X02*X10 - X00*X12;
        float c22 = X00*X11 - X01*X10;
        float det = X00*c00 + X01*c01 + X02*c02;
        float g = 1.f, gi = 1.f;
        if (it < 3) {
            // g = |det|^{-1/3}; gi = 1/g = |det|^{1/3}
            gi = cbrtf(fmaxf(fabsf(det), 1e-30f));
            g  = __fdividef(1.f, gi);
        }
        float rdet = __fdividef(0.5f * gi, det);   // 0.5 * (1/g) / det
        float hg = 0.5f * g;
        X00 = hg*X00 + c00*rdet; X01 = hg*X01 + c01*rdet; X02 = hg*X02 + c02*rdet;
        X10 = hg*X10 + c10*rdet; X11 = hg*X11 + c11*rdet; X12 = hg*X12 + c12*rdet;
        X20 = hg*X20 + c20*rdet; X21 = hg*X21 + c21*rdet; X22 = hg*X22 + c22*rdet;
    }
    // R = X; meanD = trace(R^T M3)/3
    float trH = X00*M[0][0] + X01*M[0][1] + X02*M[0][2]
              + X10*M[1][0] + X11*M[1][1] + X12*M[1][2]
              + X20*M[2][0] + X21*M[2][1] + X22*M[2][2];
    float rmd = __fdividef(3.f, trH);
    float tp0 = M[0][3]*rmd, tp1 = M[1][3]*rmd, tp2 = M[2][3]*rmd;

    float tr = X00*sGt[0] + X01*sGt[1] + X02*sGt[2]
             + X10*sGt[4] + X11*sGt[5] + X12*sGt[6]
             + X20*sGt[8] + X21*sGt[9] + X22*sGt[10];
    float cosang = fminf(fmaxf((tr - 1.f) * 0.5f, -1.f + 1e-7f), 1.f - 1e-7f);
    float rot = acosf(cosang);
    float dx = tp0 - sGt[3];
    float dy = tp1 - sGt[7];
    float dz = tp2 - sGt[11];
    float terr = sqrtf(dx*dx + dy*dy + dz*dz);

    g_per[prob] = rot + terr;
    g_cnt[prob] = sCount;
}

// ---------------------------------------------------------------------------
// Kernel 3: final scalar reduction over the 32 problems.
// ---------------------------------------------------------------------------
__global__ void k_final(float* out) {
    if (threadIdx.x == 0) {
        float tot = 0.f, cnt = 0.f;
#pragma unroll
        for (int i = 0; i < NPROB; i++) {
            float c = (g_cnt[i] >= MIN_CORR) ? 1.f : 0.f;
            tot += g_per[i] * c;
            cnt += c;
        }
        out[0] = tot / fmaxf(cnt, 1.f);
    }
}

extern "C" void kernel_launch(void* const* d_in, const int* in_sizes, int n_in,
                              void* d_out, int out_size) {
    const float* dense_b  = (const float*)d_in[1];
    const float* dense_w  = (const float*)d_in[2];
    const int*   pcls     = (const int*)  d_in[3];
    const float* Kmat     = (const float*)d_in[4];
    const float* poses    = (const float*)d_in[5];
    const float* gt       = (const float*)d_in[6];
    const float* depth    = (const float*)d_in[7];

    k_wpatch<<<2048, 256>>>(dense_b, dense_w);   // 16 patches/block, 2/warp
    k_accum<<<NPROB, 256>>>(pcls, Kmat, poses, gt, depth);
    k_final<<<1, 32>>>((float*)d_out);
}